// round 15
// baseline (speedup 1.0000x reference)
#include <cuda_runtime.h>
#include <math.h>

#define NN   512
#define FIN  256
#define HF   64
#define KTOP 12
#define LALPHA 0.2f
#define RMAX 16     // strict > kth(12th largest) gives <= 11 adjacency entries
#define UMAX 24     // union of adjacency columns and adjacency rows: <= 22
#define NEGINF -3.4e38f

// ---------------- scratch (__device__ globals; no allocation) ----------------
__device__ __align__(16) float g_A[NN * NN];            // V @ V^T
__device__ float g_cand[64 * KTOP];
__device__ unsigned g_ticket;
__device__ int   g_rowCnt[NN];
__device__ int   g_cols[NN][RMAX];
__device__ int   g_nRows;
__device__ int   g_rowIds[RMAX];
__device__ int   g_rIndexOf[NN];
__device__ int   g_nD;
__device__ int   g_dIndexOf[NN];
__device__ int   g_nU;
__device__ int   g_uList[UMAX];
__device__ int   g_uRowIdx[RMAX];
__device__ __align__(16) float g_w2[NN * FIN];
__device__ __align__(16) float g_e2h[4][NN * NN];       // split-K quarters
__device__ __align__(16) float g_WhC[NN * UMAX * HF];
__device__ __align__(16) float g_midR[RMAX * NN * HF];
__device__ __align__(16) float g_part[64 * RMAX * HF];

__device__ __forceinline__ float lrelu(float x) { return x > 0.f ? x : LALPHA * x; }
__device__ __forceinline__ float eluf(float x)  { return x > 0.f ? x : expm1f(x); }

// ---- 1) A = V @ V^T, tiled 64x64, fused per-block top-12 candidates ---------
__global__ void k_vvt_topk(const float* __restrict__ V) {
    __shared__ __align__(16) float sbuf[2 * 64 * 68];   // 34.8 KB
    float (*sViT)[68] = (float(*)[68])sbuf;             // [k][i]
    float (*sVjT)[68] = (float(*)[68])(sbuf + 64 * 68); // [k][j]
    int tid = threadIdx.x;                              // 256
    if (blockIdx.x == 0 && tid == 0) g_ticket = 0;      // reset for k_adj tail
    int bi = blockIdx.x >> 3, bj = blockIdx.x & 7;
    int i0 = bi * 64, j0 = bj * 64;
#pragma unroll
    for (int q = 0; q < 4; q++) {
        int idx = q * 1024 + tid * 4;
        int r = idx >> 6, k = idx & 63;
        float4 v = *(const float4*)(V + (size_t)(i0 + r) * HF + k);
        sViT[k][r] = v.x; sViT[k + 1][r] = v.y; sViT[k + 2][r] = v.z; sViT[k + 3][r] = v.w;
        float4 u = *(const float4*)(V + (size_t)(j0 + r) * HF + k);
        sVjT[k][r] = u.x; sVjT[k + 1][r] = u.y; sVjT[k + 2][r] = u.z; sVjT[k + 3][r] = u.w;
    }
    __syncthreads();
    int tx = tid & 15, ty = tid >> 4;
    float acc[4][4];
#pragma unroll
    for (int a = 0; a < 4; a++)
#pragma unroll
        for (int b = 0; b < 4; b++) acc[a][b] = 0.f;
#pragma unroll 8
    for (int k = 0; k < 64; k++) {
        float4 av = *(const float4*)&sViT[k][ty * 4];
        float4 bv = *(const float4*)&sVjT[k][tx * 4];
        acc[0][0] += av.x * bv.x; acc[0][1] += av.x * bv.y; acc[0][2] += av.x * bv.z; acc[0][3] += av.x * bv.w;
        acc[1][0] += av.y * bv.x; acc[1][1] += av.y * bv.y; acc[1][2] += av.y * bv.z; acc[1][3] += av.y * bv.w;
        acc[2][0] += av.z * bv.x; acc[2][1] += av.z * bv.y; acc[2][2] += av.z * bv.z; acc[2][3] += av.z * bv.w;
        acc[3][0] += av.w * bv.x; acc[3][1] += av.w * bv.y; acc[3][2] += av.w * bv.z; acc[3][3] += av.w * bv.w;
    }
#pragma unroll
    for (int a = 0; a < 4; a++)
        *(float4*)(g_A + (size_t)(i0 + ty * 4 + a) * NN + j0 + tx * 4) =
            make_float4(acc[a][0], acc[a][1], acc[a][2], acc[a][3]);
    // per-thread sorted (ascending) top-12 over the 16 register outputs
    float loc[KTOP];
#pragma unroll
    for (int k = 0; k < KTOP; k++) loc[k] = NEGINF;
#pragma unroll
    for (int a = 0; a < 4; a++)
#pragma unroll
        for (int b = 0; b < 4; b++) {
            float v = acc[a][b];
            if (v > loc[0]) {
                loc[0] = v;
#pragma unroll
                for (int k = 0; k < KTOP - 1; k++)
                    if (loc[k] > loc[k + 1]) { float t = loc[k]; loc[k] = loc[k + 1]; loc[k + 1] = t; }
            }
        }
    __syncthreads();                                    // tiles dead; overlay
    float* sLoc = sbuf;                                 // 256*12
    float* sC96 = sbuf + 256 * KTOP;                    // 96
    int lane = tid & 31, w = tid >> 5;
#pragma unroll
    for (int k = 0; k < KTOP; k++) sLoc[tid * KTOP + k] = loc[k];
    __syncwarp();
    // warp-level extract top-12 of this warp's 32x12 (no block syncs)
    int idx = KTOP - 1;
    for (int round = 0; round < KTOP; round++) {
        float val = (idx >= 0) ? sLoc[tid * KTOP + idx] : NEGINF;
        float m = val;
#pragma unroll
        for (int o = 16; o > 0; o >>= 1) m = fmaxf(m, __shfl_xor_sync(0xffffffffu, m, o));
        unsigned who = __ballot_sync(0xffffffffu, (val == m) && (idx >= 0));
        if (lane == __ffs(who) - 1) idx--;
        if (lane == 0) sC96[w * KTOP + round] = m;
    }
    __syncthreads();
    if (w == 0) {                            // merge 8x12=96 -> block top-12
        float a = sC96[lane * 3], b = sC96[lane * 3 + 1], c = sC96[lane * 3 + 2];
        float lo = fminf(a, b), hi = fmaxf(a, b);
        float l2 = fminf(lo, c), h2 = fmaxf(hi, c);
        float mid = (c < lo) ? lo : ((c > hi) ? hi : c);
        sC96[lane * 3] = l2; sC96[lane * 3 + 1] = mid; sC96[lane * 3 + 2] = h2;
        __syncwarp();
        int idx2 = 2;
        for (int round = 0; round < KTOP; round++) {
            float val = (idx2 >= 0) ? sC96[lane * 3 + idx2] : NEGINF;
            float m = val;
#pragma unroll
            for (int o = 16; o > 0; o >>= 1) m = fmaxf(m, __shfl_xor_sync(0xffffffffu, m, o));
            unsigned who = __ballot_sync(0xffffffffu, (val == m) && (idx2 >= 0));
            if (lane == __ffs(who) - 1) idx2--;
            if (lane == 0) g_cand[blockIdx.x * KTOP + round] = m;
        }
    }
}

// ---- 2) fused: kth (warp0, redundant/block) + rowscan + adj/zero writes + ---
// ----    last-block index build (ticket)                                  ---
__global__ void k_adj(float* __restrict__ adj, int hasAdj,
                      float* __restrict__ finZ, int hasFin) {
    __shared__ float sKth;
    __shared__ unsigned sMask[16];
    __shared__ int sRowIds[RMAX], sCntR[RMAX], sNR;
    __shared__ int sColsR[RMAX][RMAX];
    __shared__ int sD[NN];
    __shared__ int sLast;
    __shared__ float sL[32 * KTOP];
    int tid = threadIdx.x, lane = tid & 31, w = tid >> 5;   // 256 threads, 8 warps
    // --- exact 12th largest of g_cand[768] in warp 0, shuffle-only ---
    if (w == 0) {
        float loc[KTOP];
#pragma unroll
        for (int k = 0; k < KTOP; k++) loc[k] = NEGINF;
#pragma unroll
        for (int t = 0; t < 24; t++) {
            float v = g_cand[lane * 24 + t];
            if (v > loc[0]) {
                loc[0] = v;
#pragma unroll
                for (int k = 0; k < KTOP - 1; k++)
                    if (loc[k] > loc[k + 1]) { float tt = loc[k]; loc[k] = loc[k + 1]; loc[k + 1] = tt; }
            }
        }
#pragma unroll
        for (int k = 0; k < KTOP; k++) sL[lane * KTOP + k] = loc[k];
        __syncwarp();
        int idx = KTOP - 1; float m = NEGINF;
        for (int round = 0; round < KTOP; round++) {
            float val = (idx >= 0) ? sL[lane * KTOP + idx] : NEGINF;
            m = val;
#pragma unroll
            for (int o = 16; o > 0; o >>= 1) m = fmaxf(m, __shfl_xor_sync(0xffffffffu, m, o));
            unsigned who = __ballot_sync(0xffffffffu, (val == m) && (idx >= 0));
            if (lane == __ffs(who) - 1) idx--;
        }
        if (lane == 0) sKth = m;
    }
    __syncthreads();
    float kth = sKth;
    // --- rowscan: warp w handles row i ---
    int i = blockIdx.x * 8 + w;
    float v[16];
#pragma unroll
    for (int t = 0; t < 16; t++) v[t] = g_A[i * NN + t * 32 + lane];
    int cnt = 0;
#pragma unroll
    for (int t = 0; t < 16; t++) {
        bool p = v[t] > kth;
        if (hasAdj) adj[i * NN + t * 32 + lane] = p ? 1.f : 0.f;
        unsigned mask = __ballot_sync(0xffffffffu, p);
        if (p) {
            int pos = cnt + __popc(mask & ((1u << lane) - 1u));
            if (pos < RMAX) g_cols[i][pos] = t * 32 + lane;
        }
        cnt += __popc(mask);
    }
    if (lane == 0) g_rowCnt[i] = cnt < RMAX ? cnt : RMAX;
    // --- init index maps + zero final output ---
    int gt = blockIdx.x * 256 + tid;
    if (gt < NN) { g_rIndexOf[gt] = -1; g_dIndexOf[gt] = -1; }
    if (hasFin) {
        finZ[gt * 2]     = 0.f;
        finZ[gt * 2 + 1] = 0.f;
    }
    // --- release + ticket ---
    __threadfence();
    __syncthreads();
    if (tid == 0) sLast = (atomicAdd(&g_ticket, 1u) == 63u) ? 1 : 0;
    __syncthreads();
    if (!sLast) return;
    // --- last block: build index structures ---
    __threadfence();                        // acquire
    sD[tid] = -1; sD[tid + 256] = -1;
    unsigned m1 = __ballot_sync(0xffffffffu, g_rowCnt[w * 32 + lane] > 0);
    unsigned m2 = __ballot_sync(0xffffffffu, g_rowCnt[256 + w * 32 + lane] > 0);
    if (lane == 0) { sMask[w] = m1; sMask[8 + w] = m2; }
    __syncthreads();
    if (tid == 0) {
        int nR = 0;
        for (int g = 0; g < 16 && nR < RMAX; g++) {
            unsigned mm = sMask[g];
            while (mm && nR < RMAX) {
                int b = __ffs(mm) - 1; mm &= mm - 1;
                int r = g * 32 + b;
                g_rIndexOf[r] = nR; g_rowIds[nR] = r; sRowIds[nR] = r; nR++;
            }
        }
        sNR = nR; g_nRows = nR;
        for (int r = nR; r < RMAX; r++) sRowIds[r] = 0;
    }
    __syncthreads();
    int nR = sNR;
    {
        int rr = tid >> 4, k = tid & 15;
        if (rr < RMAX) {
            sColsR[rr][k] = g_cols[sRowIds[rr]][k];
            if (k == 0) sCntR[rr] = (rr < nR) ? g_rowCnt[sRowIds[rr]] : 0;
        }
    }
    __syncthreads();
    if (tid == 0) {
        int nD = 0;
        for (int rr = 0; rr < nR; rr++) {
            int c = sCntR[rr];
            for (int k = 0; k < c; k++) {
                int j = sColsR[rr][k];
                if (sD[j] < 0 && nD < UMAX) {
                    sD[j] = nD; g_dIndexOf[j] = nD; g_uList[nD] = j; nD++;
                }
            }
        }
        g_nD = nD;
        int nU = nD;
        for (int rr = 0; rr < nR; rr++) {
            int r = sRowIds[rr];
            if (sD[r] >= 0) g_uRowIdx[rr] = sD[r];
            else if (nU < UMAX) { g_uRowIdx[rr] = nU; g_uList[nU] = r; sD[r] = nU; nU++; }
        }
        g_nU = nU;
        for (int u = nU; u < UMAX; u++) g_uList[u] = 0;
    }
}

// ---- 3) one pass over W_stack, shared-staged tiles: WhC + w2 ---------------
#define WS_SW   (64 * 65)
#define WS_SXD  (WS_SW)
#define WS_SP   (WS_SW + UMAX * FIN)
#define WS_SA2  (WS_SP + 256)
#define WS_TOT  (WS_SA2 + HF)

template<int U>
__device__ __forceinline__ void wstack_body(float* sbuf, const float* __restrict__ X,
        const float* __restrict__ W, const float* __restrict__ a, int h, int tid, int nU) {
    float (*sW)[65] = (float(*)[65])sbuf;
    float* sXd = sbuf + WS_SXD;
    float (*sp)[4] = (float(*)[4])(sbuf + WS_SP);
    float* sa2 = sbuf + WS_SA2;
    if (tid < HF) sa2[tid] = a[h * 2 * HF + HF + tid];
    for (int idx = tid; idx < U * FIN; idx += 256) {
        int u = idx >> 8, f = idx & 255;
        sXd[u * FIN + f] = (u < nU) ? X[g_uList[u] * FIN + f] : 0.f;
    }
    int fg = tid >> 6, c = tid & 63;
    float acc[U];
#pragma unroll
    for (int u = 0; u < U; u++) acc[u] = 0.f;
    const float* Wh = W + (size_t)h * FIN * HF;
    for (int t = 0; t < 4; t++) {
        const float* tileBase = Wh + t * 64 * HF;
#pragma unroll
        for (int q = 0; q < 4; q++) {
            int idx = q * 1024 + tid * 4;
            float4 v = *(const float4*)(tileBase + idx);
            int r = idx >> 6, k = idx & 63;
            sW[r][k] = v.x; sW[r][k + 1] = v.y; sW[r][k + 2] = v.z; sW[r][k + 3] = v.w;
        }
        __syncthreads();
        int fbase = t * 64 + fg * 16;
#pragma unroll
        for (int k = 0; k < 16; k++) {
            float wv = sW[fg * 16 + k][c];
#pragma unroll
            for (int u = 0; u < U; u++) acc[u] += sXd[u * FIN + fbase + k] * wv;
        }
        int fl = tid >> 2, q2 = tid & 3;
        float s = 0.f;
#pragma unroll
        for (int cc = q2 * 16; cc < q2 * 16 + 16; cc++) s += sW[fl][cc] * sa2[cc];
        sp[fl][q2] = s;
        __syncthreads();
        if (tid < 64)
            g_w2[h * FIN + t * 64 + tid] = sp[tid][0] + sp[tid][1] + sp[tid][2] + sp[tid][3];
        __syncthreads();
    }
    float (*sRed)[HF + 1] = (float(*)[HF + 1])sbuf;
#pragma unroll
    for (int u = 0; u < U; u++) sRed[fg * U + u][c] = acc[u];
    __syncthreads();
    if (fg == 0)
#pragma unroll
        for (int u = 0; u < U; u++)
            g_WhC[(h * UMAX + u) * HF + c] =
                sRed[0 * U + u][c] + sRed[1 * U + u][c] + sRed[2 * U + u][c] + sRed[3 * U + u][c];
}

__global__ void k_wstack(const float* __restrict__ X, const float* __restrict__ W,
                         const float* __restrict__ a) {
    __shared__ __align__(16) float sbuf[WS_TOT];
    int h = blockIdx.x, tid = threadIdx.x;
    int nU = g_nU;
    if (nU <= 12)      wstack_body<12>(sbuf, X, W, a, h, tid, nU);
    else if (nU <= 16) wstack_body<16>(sbuf, X, W, a, h, tid, nU);
    else               wstack_body<UMAX>(sbuf, X, W, a, h, tid, nU);
}

// ---- 4) E2 quarters = w2 @ X^T, split-K x4: 64jx32h tile, 256 thr, 4x2/thr --
__global__ __launch_bounds__(256) void k_e2(const float* __restrict__ X) {
    __shared__ __align__(16) float sA[2][32][68];   // X:  [k][j]
    __shared__ __align__(16) float sB[2][32][36];   // w2: [k][h]
    int tid = threadIdx.x;                          // 256
    int j0 = blockIdx.x * 64, h0 = blockIdx.y * 32;
    int kz = blockIdx.z * 64;                       // K quarter
    int tx = tid & 15, ty = tid >> 4;               // tx: j/4, ty: h/2
    float acc[4][2];
#pragma unroll
    for (int a = 0; a < 4; a++) { acc[a][0] = 0.f; acc[a][1] = 0.f; }
#define E2_LOAD(cc, buf)                                                        \
    {                                                                           \
        int k0 = kz + (cc) * 32;                                                \
        _Pragma("unroll")                                                       \
        for (int l = 0; l < 2; l++) {                                           \
            int idx = l * 256 + tid;                                            \
            int row = idx >> 3, q = idx & 7;                                    \
            float4 v = *(const float4*)(X + (size_t)(j0 + row) * FIN + k0 + q * 4); \
            sA[buf][q * 4 + 0][row] = v.x; sA[buf][q * 4 + 1][row] = v.y;       \
            sA[buf][q * 4 + 2][row] = v.z; sA[buf][q * 4 + 3][row] = v.w;       \
        }                                                                       \
        {                                                                       \
            int row = tid >> 3, q = tid & 7;                                    \
            float4 v = *(const float4*)(g_w2 + (size_t)(h0 + row) * FIN + k0 + q * 4); \
            sB[buf][q * 4 + 0][row] = v.x; sB[buf][q * 4 + 1][row] = v.y;       \
            sB[buf][q * 4 + 2][row] = v.z; sB[buf][q * 4 + 3][row] = v.w;       \
        }                                                                       \
    }
    E2_LOAD(0, 0)
    __syncthreads();
#pragma unroll
    for (int c = 0; c < 2; c++) {
        int cur = c & 1;
        if (c < 1) E2_LOAD(c + 1, 1 - cur)
#pragma unroll
        for (int k = 0; k < 32; k++) {
            float4 av = *(const float4*)&sA[cur][k][tx * 4];
            float b0 = sB[cur][k][ty * 2], b1 = sB[cur][k][ty * 2 + 1];
            acc[0][0] += av.x * b0; acc[1][0] += av.y * b0;
            acc[2][0] += av.z * b0; acc[3][0] += av.w * b0;
            acc[0][1] += av.x * b1; acc[1][1] += av.y * b1;
            acc[2][1] += av.z * b1; acc[3][1] += av.w * b1;
        }
        __syncthreads();
    }
#undef E2_LOAD
    float* dst = g_e2h[blockIdx.z];
#pragma unroll
    for (int b = 0; b < 2; b++)
        *(float4*)(dst + (size_t)(h0 + ty * 2 + b) * NN + j0 + tx * 4) =
            make_float4(acc[0][b], acc[1][b], acc[2][b], acc[3][b]);
}

// --- 5) block-per-head (512 thr): factorized denominators, warp-per-slot -----
__global__ __launch_bounds__(512) void k_heads(const float* __restrict__ a_stack) {
    __shared__ float se2[NN], sP1[NN], sP2[NN];
    __shared__ float sa1[HF];
    __shared__ float sred[16];
    __shared__ float sbm;
    int h = blockIdx.x, tid = threadIdx.x, w = tid >> 5, lane = tid & 31;
    float v = ((g_e2h[0][(size_t)h * NN + tid] + g_e2h[1][(size_t)h * NN + tid])
             + g_e2h[2][(size_t)h * NN + tid]) + g_e2h[3][(size_t)h * NN + tid];
    se2[tid] = v;
    if (tid < HF) sa1[tid] = a_stack[(size_t)h * 2 * HF + tid];
    float lm = v;
#pragma unroll
    for (int o = 16; o > 0; o >>= 1) lm = fmaxf(lm, __shfl_xor_sync(0xffffffffu, lm, o));
    if (lane == 0) sred[w] = lm;
    __syncthreads();
    if (w == 0) {
        float m = sred[lane & 15];
#pragma unroll
        for (int o = 8; o > 0; o >>= 1) m = fmaxf(m, __shfl_xor_sync(0xffffffffu, m, o));
        if (lane == 0) sbm = m;
    }
    __syncthreads();
    float bmax = sbm;
    float d = v - bmax;
    sP1[tid] = __expf(d);
    sP2[tid] = __expf(0.2f * d);
    __syncthreads();
    int nR = g_nRows;
    if (w < nR) {
        int slot = w;
        int i = g_rowIds[slot], ui = g_uRowIdx[slot];
        const float* whU = g_WhC + (h * UMAX + ui) * HF;
        float p = whU[lane] * sa1[lane] + whU[lane + 32] * sa1[lane + 32];
#pragma unroll
        for (int o = 16; o > 0; o >>= 1) p += __shfl_xor_sync(0xffffffffu, p, o);
        float e1 = p;
        float sumP = 0.f, sumN = 0.f;
#pragma unroll
        for (int t = 0; t < 16; t++) {
            int j = t * 32 + lane;
            if (e1 + se2[j] > 0.f) sumP += sP1[j]; else sumN += sP2[j];
        }
#pragma unroll
        for (int o = 16; o > 0; o >>= 1) {
            sumP += __shfl_xor_sync(0xffffffffu, sumP, o);
            sumN += __shfl_xor_sync(0xffffffffu, sumN, o);
        }
        float m = lrelu(e1 + bmax);              // exact row max (lrelu monotone)
        float s = __expf(e1 + bmax - m) * sumP + __expf(0.2f * (e1 + bmax) - m) * sumN;
        int cnt = g_rowCnt[i];
        float coef = 0.f; int jd = 0;
        if (lane < cnt) {
            int j = g_cols[i][lane];
            jd = g_dIndexOf[j];
            coef = __expf(lrelu(e1 + se2[j]) - m) / s;
        }
        float acc0 = 0.f, acc1 = 0.f;
        for (int k = 0; k < cnt; k++) {
            float cf  = __shfl_sync(0xffffffffu, coef, k);
            int   jdk = __shfl_sync(0xffffffffu, jd, k);
            const float* whc = g_WhC + (h * UMAX + jdk) * HF;
            acc0 += cf * whc[lane];
            acc1 += cf * whc[lane + 32];
        }
        float* dst = g_midR + (size_t)slot * (NN * HF) + h * HF;
        dst[lane]      = eluf(acc0);
        dst[lane + 32] = eluf(acc1);
    }
}

// ---- 6) Wh2 partials = midR @ W_out, in-block k-group reduction -------------
__global__ void k_wh2(const float* __restrict__ Wout) {
    __shared__ __align__(16) float sbuf[RMAX * 512];   // 32 KB (smid, then sRed)
    float (*smid)[512] = (float(*)[512])sbuf;
    int kb = blockIdx.x, tid = threadIdx.x;
    int nR = g_nRows;
    int k0 = kb * 512;
    for (int idx = tid; idx < RMAX * 512; idx += 256) {
        int r = idx / 512, k = idx % 512;
        smid[r][k] = (r < nR) ? g_midR[(size_t)r * (NN * HF) + k0 + k] : 0.f;
    }
    __syncthreads();
    int c = tid & 63, kg = tid >> 6;
    float acc[RMAX];
#pragma unroll
    for (int r = 0; r < RMAX; r++) acc[r] = 0.f;
    for (int kk = kg * 128; kk < kg * 128 + 128; kk++) {
        float wv = Wout[(size_t)(k0 + kk) * HF + c];
#pragma unroll
        for (int r = 0; r < RMAX; r++) acc[r] += smid[r][kk] * wv;
    }
    __syncthreads();                               // smid reads done; overlay
    float (*sRed)[RMAX][HF] = (float(*)[RMAX][HF])sbuf;
#pragma unroll
    for (int r = 0; r < RMAX; r++) sRed[kg][r][c] = acc[r];
    __syncthreads();
    if (kg == 0)
#pragma unroll
        for (int r = 0; r < RMAX; r++)
            g_part[(kb * RMAX + r) * HF + c] =
                sRed[0][r][c] + sRed[1][r][c] + sRed[2][r][c] + sRed[3][r][c];
}

// ---- 7) tail: reduce 64 partials -> Wh2, e12/e22, closed-form softmax, out --
__global__ void k_tail(const float* __restrict__ aout, const float* __restrict__ V,
                       float* __restrict__ out) {
    __shared__ float sWh2[RMAX][HF];
    __shared__ float se12[RMAX], se22[RMAX];
    int tid = threadIdx.x;                         // 1024
    int r = tid >> 6, c = tid & 63;
    float acc = 0.f;
#pragma unroll 8
    for (int p = 0; p < 64; p++) acc += g_part[p * (RMAX * HF) + tid];
    sWh2[r][c] = acc;
    __syncthreads();
    int w = tid >> 5, lane = tid & 31;
    if (w < RMAX) {
        float p1 = sWh2[w][lane] * aout[lane] + sWh2[w][lane + 32] * aout[lane + 32];
        float p2 = sWh2[w][lane] * aout[HF + lane] + sWh2[w][lane + 32] * aout[HF + lane + 32];
#pragma unroll
        for (int o = 16; o > 0; o >>= 1) {
            p1 += __shfl_xor_sync(0xffffffffu, p1, o);
            p2 += __shfl_xor_sync(0xffffffffu, p2, o);
        }
        if (lane == 0) { se12[w] = p1; se22[w] = p2; }
    }
    __syncthreads();
    int nR = g_nRows;
    int slot = r;
    if (slot < nR) {
        int i = g_rowIds[slot];
        float e1 = se12[slot];
        float base = lrelu(e1);                    // cols j not in R have e2 = 0
        float m = base;
        for (int rr = 0; rr < nR; rr++) m = fmaxf(m, lrelu(e1 + se22[rr]));
        float den = (float)(NN - nR) * __expf(base - m);
        for (int rr = 0; rr < nR; rr++) den += __expf(lrelu(e1 + se22[rr]) - m);
        float acc2 = 0.f;
        int cnt = g_rowCnt[i];
        for (int k = 0; k < cnt; k++) {
            int j  = g_cols[i][k];
            int rj = g_rIndexOf[j];
            if (rj >= 0)
                acc2 += __expf(lrelu(e1 + se22[rj]) - m) / den * sWh2[rj][c];
        }
        out[i * HF + c] = eluf(V[i * HF + c] * eluf(acc2));
    }
}

// ---------------- launcher ----------------
extern "C" void kernel_launch(void* const* d_in, const int* in_sizes, int n_in,
                              void* d_out, int out_size) {
    const float* X    = (const float*)d_in[0];
    const float* Wst  = (const float*)d_in[1];
    const float* ast  = (const float*)d_in[2];
    const float* Wout = (const float*)d_in[3];
    const float* aout = (const float*)d_in[4];
    const float* V    = (const float*)d_in[5];

    float* base = (float*)d_out;
    float* adjP = nullptr;
    float* finP = nullptr;
    if (out_size >= NN * NN + NN * HF)      { adjP = base; finP = base + NN * NN; }
    else if (out_size == NN * HF)           { finP = base; }
    else if (out_size == NN * NN)           { adjP = base; }
    else                                    { finP = base; }

    k_vvt_topk<<<64, 256>>>(V);
    k_adj<<<64, 256>>>(adjP, adjP != nullptr, finP, finP != nullptr);
    if (finP) {
        k_wstack<<<NN, 256>>>(X, Wst, ast);
        k_e2<<<dim3(8, 16, 4), 256>>>(X);
        k_heads<<<NN, NN>>>(ast);
        k_wh2<<<64, 256>>>(Wout);
        k_tail<<<1, 1024>>>(aout, V, finP);
    }
}

// round 16
// speedup vs baseline: 1.0461x; 1.0461x over previous
#include <cuda_runtime.h>
#include <math.h>

#define NN   512
#define FIN  256
#define HF   64
#define KTOP 12
#define LALPHA 0.2f
#define RMAX 16     // strict > kth(12th largest) gives <= 11 adjacency entries
#define UMAX 24     // union of adjacency columns and adjacency rows: <= 22
#define NEGINF -3.4e38f

// ---------------- scratch (__device__ globals; no allocation) ----------------
__device__ __align__(16) float g_A[NN * NN];            // V @ V^T
__device__ float g_cand[64 * KTOP];
__device__ unsigned g_ticket;
__device__ int   g_rowCnt[NN];
__device__ int   g_cols[NN][RMAX];
__device__ int   g_nRows;
__device__ int   g_rowIds[RMAX];
__device__ int   g_rIndexOf[NN];
__device__ int   g_nD;
__device__ int   g_dIndexOf[NN];
__device__ int   g_nU;
__device__ int   g_uList[UMAX];
__device__ int   g_uRowIdx[RMAX];
__device__ __align__(16) float g_w2[NN * FIN];
__device__ __align__(16) float g_e2h[2][NN * NN];       // split-K halves
__device__ __align__(16) float g_WhC[NN * UMAX * HF];
__device__ __align__(16) float g_midR[RMAX * NN * HF];
__device__ __align__(16) float g_part[64 * RMAX * HF];

__device__ __forceinline__ float lrelu(float x) { return x > 0.f ? x : LALPHA * x; }
__device__ __forceinline__ float eluf(float x)  { return x > 0.f ? x : expm1f(x); }

// ---- 1) A = V @ V^T, tiled 64x64, fused per-block top-12 candidates ---------
__global__ void k_vvt_topk(const float* __restrict__ V) {
    __shared__ __align__(16) float sbuf[2 * 64 * 68];   // 34.8 KB
    float (*sViT)[68] = (float(*)[68])sbuf;             // [k][i]
    float (*sVjT)[68] = (float(*)[68])(sbuf + 64 * 68); // [k][j]
    int tid = threadIdx.x;                              // 256
    if (blockIdx.x == 0 && tid == 0) g_ticket = 0;      // reset for k_adj tail
    int bi = blockIdx.x >> 3, bj = blockIdx.x & 7;
    int i0 = bi * 64, j0 = bj * 64;
#pragma unroll
    for (int q = 0; q < 4; q++) {
        int idx = q * 1024 + tid * 4;
        int r = idx >> 6, k = idx & 63;
        float4 v = *(const float4*)(V + (size_t)(i0 + r) * HF + k);
        sViT[k][r] = v.x; sViT[k + 1][r] = v.y; sViT[k + 2][r] = v.z; sViT[k + 3][r] = v.w;
        float4 u = *(const float4*)(V + (size_t)(j0 + r) * HF + k);
        sVjT[k][r] = u.x; sVjT[k + 1][r] = u.y; sVjT[k + 2][r] = u.z; sVjT[k + 3][r] = u.w;
    }
    __syncthreads();
    int tx = tid & 15, ty = tid >> 4;
    float acc[4][4];
#pragma unroll
    for (int a = 0; a < 4; a++)
#pragma unroll
        for (int b = 0; b < 4; b++) acc[a][b] = 0.f;
#pragma unroll 8
    for (int k = 0; k < 64; k++) {
        float4 av = *(const float4*)&sViT[k][ty * 4];
        float4 bv = *(const float4*)&sVjT[k][tx * 4];
        acc[0][0] += av.x * bv.x; acc[0][1] += av.x * bv.y; acc[0][2] += av.x * bv.z; acc[0][3] += av.x * bv.w;
        acc[1][0] += av.y * bv.x; acc[1][1] += av.y * bv.y; acc[1][2] += av.y * bv.z; acc[1][3] += av.y * bv.w;
        acc[2][0] += av.z * bv.x; acc[2][1] += av.z * bv.y; acc[2][2] += av.z * bv.z; acc[2][3] += av.z * bv.w;
        acc[3][0] += av.w * bv.x; acc[3][1] += av.w * bv.y; acc[3][2] += av.w * bv.z; acc[3][3] += av.w * bv.w;
    }
#pragma unroll
    for (int a = 0; a < 4; a++)
        *(float4*)(g_A + (size_t)(i0 + ty * 4 + a) * NN + j0 + tx * 4) =
            make_float4(acc[a][0], acc[a][1], acc[a][2], acc[a][3]);
    // per-thread sorted (ascending) top-12 over the 16 register outputs
    float loc[KTOP];
#pragma unroll
    for (int k = 0; k < KTOP; k++) loc[k] = NEGINF;
#pragma unroll
    for (int a = 0; a < 4; a++)
#pragma unroll
        for (int b = 0; b < 4; b++) {
            float v = acc[a][b];
            if (v > loc[0]) {
                loc[0] = v;
#pragma unroll
                for (int k = 0; k < KTOP - 1; k++)
                    if (loc[k] > loc[k + 1]) { float t = loc[k]; loc[k] = loc[k + 1]; loc[k + 1] = t; }
            }
        }
    __syncthreads();                                    // tiles dead; overlay
    float* sLoc = sbuf;                                 // 256*12
    float* sC96 = sbuf + 256 * KTOP;                    // 96
    int lane = tid & 31, w = tid >> 5;
#pragma unroll
    for (int k = 0; k < KTOP; k++) sLoc[tid * KTOP + k] = loc[k];
    __syncwarp();
    // warp-level extract top-12 of this warp's 32x12 (no block syncs)
    int idx = KTOP - 1;
    for (int round = 0; round < KTOP; round++) {
        float val = (idx >= 0) ? sLoc[tid * KTOP + idx] : NEGINF;
        float m = val;
#pragma unroll
        for (int o = 16; o > 0; o >>= 1) m = fmaxf(m, __shfl_xor_sync(0xffffffffu, m, o));
        unsigned who = __ballot_sync(0xffffffffu, (val == m) && (idx >= 0));
        if (lane == __ffs(who) - 1) idx--;
        if (lane == 0) sC96[w * KTOP + round] = m;
    }
    __syncthreads();
    if (w == 0) {                            // merge 8x12=96 -> block top-12
        float a = sC96[lane * 3], b = sC96[lane * 3 + 1], c = sC96[lane * 3 + 2];
        float lo = fminf(a, b), hi = fmaxf(a, b);
        float l2 = fminf(lo, c), h2 = fmaxf(hi, c);
        float mid = (c < lo) ? lo : ((c > hi) ? hi : c);
        sC96[lane * 3] = l2; sC96[lane * 3 + 1] = mid; sC96[lane * 3 + 2] = h2;
        __syncwarp();
        int idx2 = 2;
        for (int round = 0; round < KTOP; round++) {
            float val = (idx2 >= 0) ? sC96[lane * 3 + idx2] : NEGINF;
            float m = val;
#pragma unroll
            for (int o = 16; o > 0; o >>= 1) m = fmaxf(m, __shfl_xor_sync(0xffffffffu, m, o));
            unsigned who = __ballot_sync(0xffffffffu, (val == m) && (idx2 >= 0));
            if (lane == __ffs(who) - 1) idx2--;
            if (lane == 0) g_cand[blockIdx.x * KTOP + round] = m;
        }
    }
}

// ---- 2) fused: kth (warp0, redundant/block) + rowscan + adj/zero writes + ---
// ----    last-block index build (ticket)                                  ---
__global__ void k_adj(float* __restrict__ adj, int hasAdj,
                      float* __restrict__ finZ, int hasFin) {
    __shared__ float sKth;
    __shared__ unsigned sMask[16];
    __shared__ int sRowIds[RMAX], sCntR[RMAX], sNR;
    __shared__ int sColsR[RMAX][RMAX];
    __shared__ int sD[NN];
    __shared__ int sLast;
    __shared__ float sL[32 * KTOP];
    int tid = threadIdx.x, lane = tid & 31, w = tid >> 5;   // 256 threads, 8 warps
    // --- exact 12th largest of g_cand[768] in warp 0, shuffle-only ---
    if (w == 0) {
        float loc[KTOP];
#pragma unroll
        for (int k = 0; k < KTOP; k++) loc[k] = NEGINF;
#pragma unroll
        for (int t = 0; t < 24; t++) {
            float v = g_cand[lane * 24 + t];
            if (v > loc[0]) {
                loc[0] = v;
#pragma unroll
                for (int k = 0; k < KTOP - 1; k++)
                    if (loc[k] > loc[k + 1]) { float tt = loc[k]; loc[k] = loc[k + 1]; loc[k + 1] = tt; }
            }
        }
#pragma unroll
        for (int k = 0; k < KTOP; k++) sL[lane * KTOP + k] = loc[k];
        __syncwarp();
        int idx = KTOP - 1; float m = NEGINF;
        for (int round = 0; round < KTOP; round++) {
            float val = (idx >= 0) ? sL[lane * KTOP + idx] : NEGINF;
            m = val;
#pragma unroll
            for (int o = 16; o > 0; o >>= 1) m = fmaxf(m, __shfl_xor_sync(0xffffffffu, m, o));
            unsigned who = __ballot_sync(0xffffffffu, (val == m) && (idx >= 0));
            if (lane == __ffs(who) - 1) idx--;
        }
        if (lane == 0) sKth = m;
    }
    __syncthreads();
    float kth = sKth;
    // --- rowscan: warp w handles row i ---
    int i = blockIdx.x * 8 + w;
    float v[16];
#pragma unroll
    for (int t = 0; t < 16; t++) v[t] = g_A[i * NN + t * 32 + lane];
    int cnt = 0;
#pragma unroll
    for (int t = 0; t < 16; t++) {
        bool p = v[t] > kth;
        if (hasAdj) adj[i * NN + t * 32 + lane] = p ? 1.f : 0.f;
        unsigned mask = __ballot_sync(0xffffffffu, p);
        if (p) {
            int pos = cnt + __popc(mask & ((1u << lane) - 1u));
            if (pos < RMAX) g_cols[i][pos] = t * 32 + lane;
        }
        cnt += __popc(mask);
    }
    if (lane == 0) g_rowCnt[i] = cnt < RMAX ? cnt : RMAX;
    // --- init index maps + zero final output ---
    int gt = blockIdx.x * 256 + tid;
    if (gt < NN) { g_rIndexOf[gt] = -1; g_dIndexOf[gt] = -1; }
    if (hasFin) {
        finZ[gt * 2]     = 0.f;
        finZ[gt * 2 + 1] = 0.f;
    }
    // --- release + ticket ---
    __threadfence();
    __syncthreads();
    if (tid == 0) sLast = (atomicAdd(&g_ticket, 1u) == 63u) ? 1 : 0;
    __syncthreads();
    if (!sLast) return;
    // --- last block: build index structures ---
    __threadfence();                        // acquire
    sD[tid] = -1; sD[tid + 256] = -1;
    unsigned m1 = __ballot_sync(0xffffffffu, g_rowCnt[w * 32 + lane] > 0);
    unsigned m2 = __ballot_sync(0xffffffffu, g_rowCnt[256 + w * 32 + lane] > 0);
    if (lane == 0) { sMask[w] = m1; sMask[8 + w] = m2; }
    __syncthreads();
    if (tid == 0) {
        int nR = 0;
        for (int g = 0; g < 16 && nR < RMAX; g++) {
            unsigned mm = sMask[g];
            while (mm && nR < RMAX) {
                int b = __ffs(mm) - 1; mm &= mm - 1;
                int r = g * 32 + b;
                g_rIndexOf[r] = nR; g_rowIds[nR] = r; sRowIds[nR] = r; nR++;
            }
        }
        sNR = nR; g_nRows = nR;
        for (int r = nR; r < RMAX; r++) sRowIds[r] = 0;
    }
    __syncthreads();
    int nR = sNR;
    {
        int rr = tid >> 4, k = tid & 15;
        if (rr < RMAX) {
            sColsR[rr][k] = g_cols[sRowIds[rr]][k];
            if (k == 0) sCntR[rr] = (rr < nR) ? g_rowCnt[sRowIds[rr]] : 0;
        }
    }
    __syncthreads();
    if (tid == 0) {
        int nD = 0;
        for (int rr = 0; rr < nR; rr++) {
            int c = sCntR[rr];
            for (int k = 0; k < c; k++) {
                int j = sColsR[rr][k];
                if (sD[j] < 0 && nD < UMAX) {
                    sD[j] = nD; g_dIndexOf[j] = nD; g_uList[nD] = j; nD++;
                }
            }
        }
        g_nD = nD;
        int nU = nD;
        for (int rr = 0; rr < nR; rr++) {
            int r = sRowIds[rr];
            if (sD[r] >= 0) g_uRowIdx[rr] = sD[r];
            else if (nU < UMAX) { g_uRowIdx[rr] = nU; g_uList[nU] = r; sD[r] = nU; nU++; }
        }
        g_nU = nU;
        for (int u = nU; u < UMAX; u++) g_uList[u] = 0;
    }
}

// ---- 3) one pass over W_stack: WhC + w2; sXd transposed [f][u] for LDS.128 --
#define WS_SW   (64 * 65)                 // sW[64][65]
#define WS_SXD  (WS_SW)                   // sXd[FIN][SXS]
#define WS_SP   (WS_SW + FIN * 24)        // sp[64][4]
#define WS_SA2  (WS_SP + 256)             // sa2[64]
#define WS_TOT  (WS_SA2 + HF)             // 10624 floats = 42.5 KB

template<int U, int SXS>
__device__ __forceinline__ void wstack_body(float* sbuf, const float* __restrict__ X,
        const float* __restrict__ W, const float* __restrict__ a, int h, int tid, int nU) {
    float (*sW)[65] = (float(*)[65])sbuf;
    float* sXd = sbuf + WS_SXD;                    // [FIN][SXS], 16B-aligned rows
    float (*sp)[4] = (float(*)[4])(sbuf + WS_SP);
    float* sa2 = sbuf + WS_SA2;
    if (tid < HF) sa2[tid] = a[h * 2 * HF + HF + tid];
    for (int idx = tid; idx < U * FIN; idx += 256) {
        int u = idx >> 8, f = idx & 255;           // consecutive tid -> consecutive f
        sXd[f * SXS + u] = (u < nU) ? X[g_uList[u] * FIN + f] : 0.f;
    }
    int fg = tid >> 6, c = tid & 63;
    float acc[U];
#pragma unroll
    for (int u = 0; u < U; u++) acc[u] = 0.f;
    const float* Wh = W + (size_t)h * FIN * HF;
    for (int t = 0; t < 4; t++) {
        const float* tileBase = Wh + t * 64 * HF;
#pragma unroll
        for (int q = 0; q < 4; q++) {
            int idx = q * 1024 + tid * 4;
            float4 v = *(const float4*)(tileBase + idx);
            int r = idx >> 6, k = idx & 63;
            sW[r][k] = v.x; sW[r][k + 1] = v.y; sW[r][k + 2] = v.z; sW[r][k + 3] = v.w;
        }
        __syncthreads();                 // covers sXd/sa2 population on t==0
        int fbase = t * 64 + fg * 16;
#pragma unroll
        for (int k = 0; k < 16; k++) {
            float wv = sW[fg * 16 + k][c];
            const float* xr = sXd + (fbase + k) * SXS;
#pragma unroll
            for (int q4 = 0; q4 < U / 4; q4++) {
                float4 xv = *(const float4*)(xr + q4 * 4);    // broadcast LDS.128
                acc[q4 * 4 + 0] += xv.x * wv;
                acc[q4 * 4 + 1] += xv.y * wv;
                acc[q4 * 4 + 2] += xv.z * wv;
                acc[q4 * 4 + 3] += xv.w * wv;
            }
        }
        int fl = tid >> 2, q2 = tid & 3;
        float s = 0.f;
#pragma unroll
        for (int cc = q2 * 16; cc < q2 * 16 + 16; cc++) s += sW[fl][cc] * sa2[cc];
        sp[fl][q2] = s;
        __syncthreads();
        if (tid < 64)
            g_w2[h * FIN + t * 64 + tid] = sp[tid][0] + sp[tid][1] + sp[tid][2] + sp[tid][3];
        __syncthreads();                 // before next tile overwrites sW/sp
    }
    float (*sRed)[HF + 1] = (float(*)[HF + 1])sbuf;    // [4*U][65], overlays sW/sXd
#pragma unroll
    for (int u = 0; u < U; u++) sRed[fg * U + u][c] = acc[u];
    __syncthreads();
    if (fg == 0)
#pragma unroll
        for (int u = 0; u < U; u++)
            g_WhC[(h * UMAX + u) * HF + c] =
                sRed[0 * U + u][c] + sRed[1 * U + u][c] + sRed[2 * U + u][c] + sRed[3 * U + u][c];
}

__global__ void k_wstack(const float* __restrict__ X, const float* __restrict__ W,
                         const float* __restrict__ a) {
    __shared__ __align__(16) float sbuf[WS_TOT];
    int h = blockIdx.x, tid = threadIdx.x;   // 256 threads
    int nU = g_nU;
    if (nU <= 12)      wstack_body<12, 16>(sbuf, X, W, a, h, tid, nU);
    else if (nU <= 16) wstack_body<16, 16>(sbuf, X, W, a, h, tid, nU);
    else               wstack_body<UMAX, 24>(sbuf, X, W, a, h, tid, nU);
}

// ---- 4) E2 halves = w2 @ X^T, split-K x2: 64jx32h tile, 256 thr, 4x2/thr ----
__global__ __launch_bounds__(256) void k_e2(const float* __restrict__ X) {
    __shared__ __align__(16) float sA[2][32][68];   // X:  [k][j]
    __shared__ __align__(16) float sB[2][32][36];   // w2: [k][h]
    int tid = threadIdx.x;                          // 256
    int j0 = blockIdx.x * 64, h0 = blockIdx.y * 32;
    int kz = blockIdx.z * 128;                      // K half
    int tx = tid & 15, ty = tid >> 4;               // tx: j/4, ty: h/2
    float acc[4][2];
#pragma unroll
    for (int a = 0; a < 4; a++) { acc[a][0] = 0.f; acc[a][1] = 0.f; }
#define E2_LOAD(cc, buf)                                                        \
    {                                                                           \
        int k0 = kz + (cc) * 32;                                                \
        _Pragma("unroll")                                                       \
        for (int l = 0; l < 2; l++) {                                           \
            int idx = l * 256 + tid;                                            \
            int row = idx >> 3, q = idx & 7;                                    \
            float4 v = *(const float4*)(X + (size_t)(j0 + row) * FIN + k0 + q * 4); \
            sA[buf][q * 4 + 0][row] = v.x; sA[buf][q * 4 + 1][row] = v.y;       \
            sA[buf][q * 4 + 2][row] = v.z; sA[buf][q * 4 + 3][row] = v.w;       \
        }                                                                       \
        {                                                                       \
            int row = tid >> 3, q = tid & 7;                                    \
            float4 v = *(const float4*)(g_w2 + (size_t)(h0 + row) * FIN + k0 + q * 4); \
            sB[buf][q * 4 + 0][row] = v.x; sB[buf][q * 4 + 1][row] = v.y;       \
            sB[buf][q * 4 + 2][row] = v.z; sB[buf][q * 4 + 3][row] = v.w;       \
        }                                                                       \
    }
    E2_LOAD(0, 0)
    __syncthreads();
#pragma unroll
    for (int c = 0; c < 4; c++) {
        int cur = c & 1;
        if (c < 3) E2_LOAD(c + 1, 1 - cur)
#pragma unroll
        for (int k = 0; k < 32; k++) {
            float4 av = *(const float4*)&sA[cur][k][tx * 4];
            float b0 = sB[cur][k][ty * 2], b1 = sB[cur][k][ty * 2 + 1];
            acc[0][0] += av.x * b0; acc[1][0] += av.y * b0;
            acc[2][0] += av.z * b0; acc[3][0] += av.w * b0;
            acc[0][1] += av.x * b1; acc[1][1] += av.y * b1;
            acc[2][1] += av.z * b1; acc[3][1] += av.w * b1;
        }
        __syncthreads();
    }
#undef E2_LOAD
    float* dst = g_e2h[blockIdx.z];
#pragma unroll
    for (int b = 0; b < 2; b++)
        *(float4*)(dst + (size_t)(h0 + ty * 2 + b) * NN + j0 + tx * 4) =
            make_float4(acc[0][b], acc[1][b], acc[2][b], acc[3][b]);
}

// --- 5) block-per-head (512 thr): factorized denominators, warp-per-slot -----
__global__ __launch_bounds__(512) void k_heads(const float* __restrict__ a_stack) {
    __shared__ float se2[NN], sP1[NN], sP2[NN];
    __shared__ float sa1[HF];
    __shared__ float sred[16];
    __shared__ float sbm;
    int h = blockIdx.x, tid = threadIdx.x, w = tid >> 5, lane = tid & 31;
    float v = g_e2h[0][(size_t)h * NN + tid] + g_e2h[1][(size_t)h * NN + tid];
    se2[tid] = v;
    if (tid < HF) sa1[tid] = a_stack[(size_t)h * 2 * HF + tid];
    float lm = v;
#pragma unroll
    for (int o = 16; o > 0; o >>= 1) lm = fmaxf(lm, __shfl_xor_sync(0xffffffffu, lm, o));
    if (lane == 0) sred[w] = lm;
    __syncthreads();
    if (w == 0) {
        float m = sred[lane & 15];
#pragma unroll
        for (int o = 8; o > 0; o >>= 1) m = fmaxf(m, __shfl_xor_sync(0xffffffffu, m, o));
        if (lane == 0) sbm = m;
    }
    __syncthreads();
    float bmax = sbm;
    float d = v - bmax;
    sP1[tid] = __expf(d);
    sP2[tid] = __expf(0.2f * d);
    __syncthreads();
    int nR = g_nRows;
    if (w < nR) {
        int slot = w;
        int i = g_rowIds[slot], ui = g_uRowIdx[slot];
        const float* whU = g_WhC + (h * UMAX + ui) * HF;
        float p = whU[lane] * sa1[lane] + whU[lane + 32] * sa1[lane + 32];
#pragma unroll
        for (int o = 16; o > 0; o >>= 1) p += __shfl_xor_sync(0xffffffffu, p, o);
        float e1 = p;
        float sumP = 0.f, sumN = 0.f;
#pragma unroll
        for (int t = 0; t < 16; t++) {
            int j = t * 32 + lane;
            if (e1 + se2[j] > 0.f) sumP += sP1[j]; else sumN += sP2[j];
        }
#pragma unroll
        for (int o = 16; o > 0; o >>= 1) {
            sumP += __shfl_xor_sync(0xffffffffu, sumP, o);
            sumN += __shfl_xor_sync(0xffffffffu, sumN, o);
        }
        float m = lrelu(e1 + bmax);              // exact row max (lrelu monotone)
        float s = __expf(e1 + bmax - m) * sumP + __expf(0.2f * (e1 + bmax) - m) * sumN;
        int cnt = g_rowCnt[i];
        float coef = 0.f; int jd = 0;
        if (lane < cnt) {
            int j = g_cols[i][lane];
            jd = g_dIndexOf[j];
            coef = __expf(lrelu(e1 + se2[j]) - m) / s;
        }
        float acc0 = 0.f, acc1 = 0.f;
        for (int k = 0; k < cnt; k++) {
            float cf  = __shfl_sync(0xffffffffu, coef, k);
            int   jdk = __shfl_sync(0xffffffffu, jd, k);
            const float* whc = g_WhC + (h * UMAX + jdk) * HF;
            acc0 += cf * whc[lane];
            acc1 += cf * whc[lane + 32];
        }
        float* dst = g_midR + (size_t)slot * (NN * HF) + h * HF;
        dst[lane]      = eluf(acc0);
        dst[lane + 32] = eluf(acc1);
    }
}

// ---- 6) Wh2 partials = midR @ W_out, in-block k-group reduction -------------
__global__ void k_wh2(const float* __restrict__ Wout) {
    __shared__ __align__(16) float sbuf[RMAX * 512];   // 32 KB (smid, then sRed)
    float (*smid)[512] = (float(*)[512])sbuf;
    int kb = blockIdx.x, tid = threadIdx.x;
    int nR = g_nRows;
    int k0 = kb * 512;
    for (int idx = tid; idx < RMAX * 512; idx += 256) {
        int r = idx / 512, k = idx % 512;
        smid[r][k] = (r < nR) ? g_midR[(size_t)r * (NN * HF) + k0 + k] : 0.f;
    }
    __syncthreads();
    int c = tid & 63, kg = tid >> 6;
    float acc[RMAX];
#pragma unroll
    for (int r = 0; r < RMAX; r++) acc[r] = 0.f;
    for (int kk = kg * 128; kk < kg * 128 + 128; kk++) {
        float wv = Wout[(size_t)(k0 + kk) * HF + c];
#pragma unroll
        for (int r = 0; r < RMAX; r++) acc[r] += smid[r][kk] * wv;
    }
    __syncthreads();                               // smid reads done; overlay
    float (*sRed)[RMAX][HF] = (float(*)[RMAX][HF])sbuf;
#pragma unroll
    for (int r = 0; r < RMAX; r++) sRed[kg][r][c] = acc[r];
    __syncthreads();
    if (kg == 0)
#pragma unroll
        for (int r = 0; r < RMAX; r++)
            g_part[(kb * RMAX + r) * HF + c] =
                sRed[0][r][c] + sRed[1][r][c] + sRed[2][r][c] + sRed[3][r][c];
}

// ---- 7) tail: reduce 64 partials -> Wh2, e12/e22, closed-form softmax, out --
__global__ void k_tail(const float* __restrict__ aout, const float* __restrict__ V,
                       float* __restrict__ out) {
    __shared__ float sWh2[RMAX][HF];
    __shared__ float se12[RMAX], se22[RMAX];
    int tid = threadIdx.x;                         // 1024
    int r = tid >> 6, c = tid & 63;
    float acc = 0.f;
#pragma unroll 8
    for (int p = 0; p < 64; p++) acc += g_part[p * (RMAX * HF) + tid];
    sWh2[r][c] = acc;
    __syncthreads();
    int w = tid >> 5, lane = tid & 31;
    if (w < RMAX) {
        float p1 = sWh2[w][lane] * aout[lane] + sWh2[w][lane + 32] * aout[lane + 32];
        float p2 = sWh2[w][lane] * aout[HF + lane] + sWh2[w][lane + 32] * aout[HF + lane + 32];
#pragma unroll
        for (int o = 16; o > 0; o >>= 1) {
            p1 += __shfl_xor_sync(0xffffffffu, p1, o);
            p2 += __shfl_xor_sync(0xffffffffu, p2, o);
        }
        if (lane == 0) { se12[w] = p1; se22[w] = p2; }
    }
    __syncthreads();
    int nR = g_nRows;
    int slot = r;
    if (slot < nR) {
        int i = g_rowIds[slot];
        float e1 = se12[slot];
        float base = lrelu(e1);                    // cols j not in R have e2 = 0
        float m = base;
        for (int rr = 0; rr < nR; rr++) m = fmaxf(m, lrelu(e1 + se22[rr]));
        float den = (float)(NN - nR) * __expf(base - m);
        for (int rr = 0; rr < nR; rr++) den += __expf(lrelu(e1 + se22[rr]) - m);
        float acc2 = 0.f;
        int cnt = g_rowCnt[i];
        for (int k = 0; k < cnt; k++) {
            int j  = g_cols[i][k];
            int rj = g_rIndexOf[j];
            if (rj >= 0)
                acc2 += __expf(lrelu(e1 + se22[rj]) - m) / den * sWh2[rj][c];
        }
        out[i * HF + c] = eluf(V[i * HF + c] * eluf(acc2));
    }
}

// ---------------- launcher ----------------
extern "C" void kernel_launch(void* const* d_in, const int* in_sizes, int n_in,
                              void* d_out, int out_size) {
    const float* X    = (const float*)d_in[0];
    const float* Wst  = (const float*)d_in[1];
    const float* ast  = (const float*)d_in[2];
    const float* Wout = (const float*)d_in[3];
    const float* aout = (const float*)d_in[4];
    const float* V    = (const float*)d_in[5];

    float* base = (float*)d_out;
    float* adjP = nullptr;
    float* finP = nullptr;
    if (out_size >= NN * NN + NN * HF)      { adjP = base; finP = base + NN * NN; }
    else if (out_size == NN * HF)           { finP = base; }
    else if (out_size == NN * NN)           { adjP = base; }
    else                                    { finP = base; }

    k_vvt_topk<<<64, 256>>>(V);
    k_adj<<<64, 256>>>(adjP, adjP != nullptr, finP, finP != nullptr);
    if (finP) {
        k_wstack<<<NN, 256>>>(X, Wst, ast);
        k_e2<<<dim3(8, 16, 2), 256>>>(X);
        k_heads<<<NN, NN>>>(ast);
        k_wh2<<<64, 256>>>(Wout);
        k_tail<<<1, 1024>>>(aout, V, finP);
    }
}